// round 3
// baseline (speedup 1.0000x reference)
#include <cuda_runtime.h>

// ---------------------------------------------------------------------------
// TransferSH: per-point SH(deg3) evaluation + gathered SH-coefficient dot
// product + tiny global MLP-derived affine color transform.
//
// Output layout (float32): [ clipped colors (N*3) , mean_abs scalar (1) ]
// ---------------------------------------------------------------------------

#define N_POINTS 2000000

__device__ float g_affine[12];   // row-major 3x4, eye added

// SH constants
#define SH_C0 0.28209479177387814f
#define SH_C1 0.4886025119029199f
#define SH_C2_0 1.0925484305920792f
#define SH_C2_1 (-1.0925484305920792f)
#define SH_C2_2 0.31539156525252005f
#define SH_C2_3 (-1.0925484305920792f)
#define SH_C2_4 0.5462742152960396f
#define SH_C3_0 (-0.5900435899266435f)
#define SH_C3_1 2.890611442640554f
#define SH_C3_2 (-0.4570457994644658f)
#define SH_C3_3 0.3731763325901154f
#define SH_C3_4 (-0.4570457994644658f)
#define SH_C3_5 1.445305721320277f
#define SH_C3_6 (-0.5900435899266435f)

// ---------------------------------------------------------------------------
// Kernel A: the 1x16 -> 32 (LN, relu) -> 12 MLP, affine build, mean|.|
// Trivial amount of work: single thread.
// ---------------------------------------------------------------------------
__global__ void affine_kernel(const float* __restrict__ glo,     // (1,16)
                              const float* __restrict__ w1,      // (16,32)
                              const float* __restrict__ b1,      // (32,)
                              const float* __restrict__ ln_w,    // (32,)
                              const float* __restrict__ ln_b,    // (32,)
                              const float* __restrict__ w2,      // (32,12)
                              const float* __restrict__ b2,      // (12,)
                              float* __restrict__ out_scalar)
{
    if (threadIdx.x != 0 || blockIdx.x != 0) return;

    float g[16];
#pragma unroll
    for (int k = 0; k < 16; k++) g[k] = glo[k];

    float h[32];
    float mu = 0.f;
#pragma unroll
    for (int j = 0; j < 32; j++) {
        float acc = b1[j];
#pragma unroll
        for (int k = 0; k < 16; k++) acc += g[k] * w1[k * 32 + j];
        h[j] = acc;
        mu += acc;
    }
    mu *= (1.f / 32.f);
    float var = 0.f;
#pragma unroll
    for (int j = 0; j < 32; j++) {
        float d = h[j] - mu;
        var += d * d;
    }
    var *= (1.f / 32.f);
    float inv = rsqrtf(var + 1e-5f);
#pragma unroll
    for (int j = 0; j < 32; j++) {
        float v = (h[j] - mu) * inv * ln_w[j] + ln_b[j];
        h[j] = v > 0.f ? v : 0.f;
    }

    float s = 0.f;
#pragma unroll
    for (int c = 0; c < 12; c++) {
        float o = b2[c];
#pragma unroll
        for (int j = 0; j < 32; j++) o += h[j] * w2[j * 12 + c];
        o *= 1e-12f;
        s += fabsf(o);
        g_affine[c] = o;
    }
    // + eye(3,4): flat indices 0, 5, 10
    g_affine[0] += 1.f;
    g_affine[5] += 1.f;
    g_affine[10] += 1.f;

    *out_scalar = s * (1.f / 12.f);
}

// ---------------------------------------------------------------------------
// Kernel B: per-point SH evaluation + gather + affine + clamp
// ---------------------------------------------------------------------------
__global__ void __launch_bounds__(256)
transfer_sh_kernel(const float* __restrict__ positions,   // (N,3)
                   const int*   __restrict__ indexes,     // (N,)
                   const float* __restrict__ cam_pos,     // (3,)
                   const float* __restrict__ base_sh,     // (NP,3,1)
                   const float* __restrict__ higher_sh,   // (NP,3,15)
                   float*       __restrict__ out,         // (N,3)
                   int n)
{
    int i = blockIdx.x * blockDim.x + threadIdx.x;
    if (i >= n) return;

    float cx = __ldg(cam_pos + 0);
    float cy = __ldg(cam_pos + 1);
    float cz = __ldg(cam_pos + 2);

    float dx = __ldg(positions + 3 * i + 0) - cx;
    float dy = __ldg(positions + 3 * i + 1) - cy;
    float dz = __ldg(positions + 3 * i + 2) - cz;
    float rinv = rsqrtf(dx * dx + dy * dy + dz * dz);
    float x = dx * rinv, y = dy * rinv, z = dz * rinv;

    float xx = x * x, yy = y * y, zz = z * z;
    float xy = x * y, yz = y * z, xz = x * z;

    float basis[16];
    basis[0]  = SH_C0;
    basis[1]  = -SH_C1 * y;
    basis[2]  =  SH_C1 * z;
    basis[3]  = -SH_C1 * x;
    basis[4]  = SH_C2_0 * xy;
    basis[5]  = SH_C2_1 * yz;
    basis[6]  = SH_C2_2 * (2.f * zz - xx - yy);
    basis[7]  = SH_C2_3 * xz;
    basis[8]  = SH_C2_4 * (xx - yy);
    basis[9]  = SH_C3_0 * y * (3.f * xx - yy);
    basis[10] = SH_C3_1 * xy * z;
    basis[11] = SH_C3_2 * y * (4.f * zz - xx - yy);
    basis[12] = SH_C3_3 * z * (2.f * zz - 3.f * xx - 3.f * yy);
    basis[13] = SH_C3_4 * x * (4.f * zz - xx - yy);
    basis[14] = SH_C3_5 * z * (xx - yy);
    basis[15] = SH_C3_6 * x * (xx - yy);

    long long id = __ldg(indexes + i);
    const float* brow = base_sh + id * 3;
    const float* hrow = higher_sh + id * 45;

    float col[3];
#pragma unroll
    for (int c = 0; c < 3; c++) {
        float acc = __ldg(brow + c) * basis[0];
#pragma unroll
        for (int k = 0; k < 15; k++)
            acc += __ldg(hrow + c * 15 + k) * basis[k + 1];
        col[c] = acc + 0.5f;
    }

    // affine: out_r = a[r][0]*c0 + a[r][1]*c1 + a[r][2]*c2 + a[r][3]
#pragma unroll
    for (int r = 0; r < 3; r++) {
        float o = g_affine[r * 4 + 0] * col[0]
                + g_affine[r * 4 + 1] * col[1]
                + g_affine[r * 4 + 2] * col[2]
                + g_affine[r * 4 + 3];
        o = fminf(fmaxf(o, 0.f), 1.f);
        out[3 * i + r] = o;
    }
}

// ---------------------------------------------------------------------------
// kernel_launch
// input order: positions, indexes, cam_pos, glo_feature, base_sh, higher_sh,
//              w1, b1, ln_w, ln_b, w2, b2
// ---------------------------------------------------------------------------
extern "C" void kernel_launch(void* const* d_in, const int* in_sizes, int n_in,
                              void* d_out, int out_size)
{
    const float* positions = (const float*)d_in[0];
    const int*   indexes   = (const int*)  d_in[1];
    const float* cam_pos   = (const float*)d_in[2];
    const float* glo       = (const float*)d_in[3];
    const float* base_sh   = (const float*)d_in[4];
    const float* higher_sh = (const float*)d_in[5];
    const float* w1        = (const float*)d_in[6];
    const float* b1        = (const float*)d_in[7];
    const float* ln_w      = (const float*)d_in[8];
    const float* ln_b      = (const float*)d_in[9];
    const float* w2        = (const float*)d_in[10];
    const float* b2        = (const float*)d_in[11];

    float* out = (float*)d_out;
    int n = in_sizes[0] / 3;   // positions is (N,3)

    // scalar goes at the end of the output buffer
    float* out_scalar = out + (out_size - 1);

    affine_kernel<<<1, 32>>>(glo, w1, b1, ln_w, ln_b, w2, b2, out_scalar);

    int threads = 256;
    int blocks = (n + threads - 1) / threads;
    transfer_sh_kernel<<<blocks, threads>>>(positions, indexes, cam_pos,
                                            base_sh, higher_sh, out, n);
}

// round 4
// speedup vs baseline: 1.6577x; 1.6577x over previous
#include <cuda_runtime.h>

// ---------------------------------------------------------------------------
// TransferSH: per-point SH(deg3) evaluation + gathered SH-coefficient dot
// product + tiny global MLP-derived affine color transform.
//
// R3: vectorized gather. higher_sh rows are 45 floats (180 B) at alignment
// class (id mod 4). Load a 12 x float4 aligned window covering the row and
// consume with compile-time offsets (4-way switch) -> 12 LDG.128 instead of
// 45 LDG.32, cutting L1tex wavefront pressure ~4x on the dominant stream.
//
// Output layout (float32): [ clipped colors (N*3) , mean_abs scalar (1) ]
// ---------------------------------------------------------------------------

__device__ float g_affine[12];   // row-major 3x4, eye added

// SH constants
#define SH_C0 0.28209479177387814f
#define SH_C1 0.4886025119029199f
#define SH_C2_0 1.0925484305920792f
#define SH_C2_1 (-1.0925484305920792f)
#define SH_C2_2 0.31539156525252005f
#define SH_C2_3 (-1.0925484305920792f)
#define SH_C2_4 0.5462742152960396f
#define SH_C3_0 (-0.5900435899266435f)
#define SH_C3_1 2.890611442640554f
#define SH_C3_2 (-0.4570457994644658f)
#define SH_C3_3 0.3731763325901154f
#define SH_C3_4 (-0.4570457994644658f)
#define SH_C3_5 1.445305721320277f
#define SH_C3_6 (-0.5900435899266435f)

// ---------------------------------------------------------------------------
// Kernel A: the 1x16 -> 32 (LN, relu) -> 12 MLP, affine build, mean|.|
// ---------------------------------------------------------------------------
__global__ void affine_kernel(const float* __restrict__ glo,
                              const float* __restrict__ w1,
                              const float* __restrict__ b1,
                              const float* __restrict__ ln_w,
                              const float* __restrict__ ln_b,
                              const float* __restrict__ w2,
                              const float* __restrict__ b2,
                              float* __restrict__ out_scalar)
{
    if (threadIdx.x != 0 || blockIdx.x != 0) return;

    float g[16];
#pragma unroll
    for (int k = 0; k < 16; k++) g[k] = glo[k];

    float h[32];
    float mu = 0.f;
#pragma unroll
    for (int j = 0; j < 32; j++) {
        float acc = b1[j];
#pragma unroll
        for (int k = 0; k < 16; k++) acc += g[k] * w1[k * 32 + j];
        h[j] = acc;
        mu += acc;
    }
    mu *= (1.f / 32.f);
    float var = 0.f;
#pragma unroll
    for (int j = 0; j < 32; j++) {
        float d = h[j] - mu;
        var += d * d;
    }
    var *= (1.f / 32.f);
    float inv = rsqrtf(var + 1e-5f);
#pragma unroll
    for (int j = 0; j < 32; j++) {
        float v = (h[j] - mu) * inv * ln_w[j] + ln_b[j];
        h[j] = v > 0.f ? v : 0.f;
    }

    float s = 0.f;
#pragma unroll
    for (int c = 0; c < 12; c++) {
        float o = b2[c];
#pragma unroll
        for (int j = 0; j < 32; j++) o += h[j] * w2[j * 12 + c];
        o *= 1e-12f;
        s += fabsf(o);
        g_affine[c] = o;
    }
    g_affine[0]  += 1.f;
    g_affine[5]  += 1.f;
    g_affine[10] += 1.f;

    *out_scalar = s * (1.f / 12.f);
}

// ---------------------------------------------------------------------------
// Templated gather+accumulate: OFF is the float offset (0..3) of the row start
// within the aligned 12 x float4 window. All indexing is compile-time constant
// so the 48-float window lives in registers.
// ---------------------------------------------------------------------------
template<int OFF>
__device__ __forceinline__ void gather_accum(const float4* __restrict__ q,
                                             const float* __restrict__ basis,
                                             float* __restrict__ col)
{
    float f[48];
#pragma unroll
    for (int j = 0; j < 12; j++) {
        float4 t = __ldg(q + j);
        f[4 * j + 0] = t.x;
        f[4 * j + 1] = t.y;
        f[4 * j + 2] = t.z;
        f[4 * j + 3] = t.w;
    }
#pragma unroll
    for (int c = 0; c < 3; c++) {
        float acc = 0.f;
#pragma unroll
        for (int k = 0; k < 15; k++)
            acc += f[OFF + c * 15 + k] * basis[k + 1];
        col[c] += acc;
    }
}

// ---------------------------------------------------------------------------
// Kernel B: per-point SH evaluation + gather + affine + clamp
// ---------------------------------------------------------------------------
__global__ void __launch_bounds__(256)
transfer_sh_kernel(const float* __restrict__ positions,   // (N,3)
                   const int*   __restrict__ indexes,     // (N,)
                   const float* __restrict__ cam_pos,     // (3,)
                   const float* __restrict__ base_sh,     // (NP,3,1)
                   const float* __restrict__ higher_sh,   // (NP,3,15)
                   float*       __restrict__ out,         // (N,3)
                   int n)
{
    int i = blockIdx.x * blockDim.x + threadIdx.x;
    if (i >= n) return;

    float cx = __ldg(cam_pos + 0);
    float cy = __ldg(cam_pos + 1);
    float cz = __ldg(cam_pos + 2);

    float dx = __ldg(positions + 3 * i + 0) - cx;
    float dy = __ldg(positions + 3 * i + 1) - cy;
    float dz = __ldg(positions + 3 * i + 2) - cz;
    float rinv = rsqrtf(dx * dx + dy * dy + dz * dz);
    float x = dx * rinv, y = dy * rinv, z = dz * rinv;

    float xx = x * x, yy = y * y, zz = z * z;
    float xy = x * y, yz = y * z, xz = x * z;

    float basis[16];
    basis[0]  = SH_C0;
    basis[1]  = -SH_C1 * y;
    basis[2]  =  SH_C1 * z;
    basis[3]  = -SH_C1 * x;
    basis[4]  = SH_C2_0 * xy;
    basis[5]  = SH_C2_1 * yz;
    basis[6]  = SH_C2_2 * (2.f * zz - xx - yy);
    basis[7]  = SH_C2_3 * xz;
    basis[8]  = SH_C2_4 * (xx - yy);
    basis[9]  = SH_C3_0 * y * (3.f * xx - yy);
    basis[10] = SH_C3_1 * xy * z;
    basis[11] = SH_C3_2 * y * (4.f * zz - xx - yy);
    basis[12] = SH_C3_3 * z * (2.f * zz - 3.f * xx - 3.f * yy);
    basis[13] = SH_C3_4 * x * (4.f * zz - xx - yy);
    basis[14] = SH_C3_5 * z * (xx - yy);
    basis[15] = SH_C3_6 * x * (xx - yy);

    int id = __ldg(indexes + i);

    // base_sh: 3 floats at float-offset 3*id (12B rows; keep scalar loads)
    const float* brow = base_sh + (long long)id * 3;
    float col[3];
    col[0] = __ldg(brow + 0) * basis[0] + 0.5f;
    col[1] = __ldg(brow + 1) * basis[0] + 0.5f;
    col[2] = __ldg(brow + 2) * basis[0] + 0.5f;

    // higher_sh: 45 floats starting at float-offset 45*id.
    // Aligned float4 window: q = &higher_sh[4 * floor(45*id/4)], row offset
    // within window = (45*id) mod 4 = id mod 4. Window covers off+45 <= 48
    // floats and never crosses the array end (max end exactly 90M floats).
    long long fstart = (long long)id * 45;
    const float4* q = (const float4*)higher_sh + (fstart >> 2);
    int off = (int)(fstart & 3);

    switch (off) {
        case 0: gather_accum<0>(q, basis, col); break;
        case 1: gather_accum<1>(q, basis, col); break;
        case 2: gather_accum<2>(q, basis, col); break;
        default: gather_accum<3>(q, basis, col); break;
    }

    // affine: out_r = a[r][0]*c0 + a[r][1]*c1 + a[r][2]*c2 + a[r][3]
#pragma unroll
    for (int r = 0; r < 3; r++) {
        float o = g_affine[r * 4 + 0] * col[0]
                + g_affine[r * 4 + 1] * col[1]
                + g_affine[r * 4 + 2] * col[2]
                + g_affine[r * 4 + 3];
        o = fminf(fmaxf(o, 0.f), 1.f);
        out[3 * i + r] = o;
    }
}

// ---------------------------------------------------------------------------
// kernel_launch
// input order: positions, indexes, cam_pos, glo_feature, base_sh, higher_sh,
//              w1, b1, ln_w, ln_b, w2, b2
// ---------------------------------------------------------------------------
extern "C" void kernel_launch(void* const* d_in, const int* in_sizes, int n_in,
                              void* d_out, int out_size)
{
    const float* positions = (const float*)d_in[0];
    const int*   indexes   = (const int*)  d_in[1];
    const float* cam_pos   = (const float*)d_in[2];
    const float* glo       = (const float*)d_in[3];
    const float* base_sh   = (const float*)d_in[4];
    const float* higher_sh = (const float*)d_in[5];
    const float* w1        = (const float*)d_in[6];
    const float* b1        = (const float*)d_in[7];
    const float* ln_w      = (const float*)d_in[8];
    const float* ln_b      = (const float*)d_in[9];
    const float* w2        = (const float*)d_in[10];
    const float* b2        = (const float*)d_in[11];

    float* out = (float*)d_out;
    int n = in_sizes[0] / 3;   // positions is (N,3)

    float* out_scalar = out + (out_size - 1);

    affine_kernel<<<1, 32>>>(glo, w1, b1, ln_w, ln_b, w2, b2, out_scalar);

    int threads = 256;
    int blocks = (n + threads - 1) / threads;
    transfer_sh_kernel<<<blocks, threads>>>(positions, indexes, cam_pos,
                                            base_sh, higher_sh, out, n);
}